// round 4
// baseline (speedup 1.0000x reference)
#include <cuda_runtime.h>
#include <cuda_bf16.h>
#include <cstdio>

// ---------------------------------------------------------------------------
// DLRM forward, fp32 baseline.
//   x [16384,39] = 13 dense + 26 categorical (float-encoded ids)
//   bottom MLP 13->512->256->128 (relu)
//   feat = [bot_out ; emb[idx]] -> [B,27,128]; inter = triu(f f^T) -> [B,378]
//   t0 = [bot_out, inter] -> [B,506]  (stored with stride 512)
//   top MLP 506->1024->1024->512->256->1 (relu except last)
// ---------------------------------------------------------------------------

#define BATCH   16384
#define NDENSE  13
#define NSPARSE 26
#define XCOLS   39
#define EMBDIM  128
#define VOCAB   1000000
#define NFEAT   27     // 1 + 26
#define T0LD    512    // padded leading dim for the 506-wide top input

// -------------------- scratch (device globals; no allocation) --------------
__device__ float g_h1 [BATCH * 512];
__device__ float g_h2 [BATCH * 256];
__device__ float g_bot[BATCH * 128];
__device__ float g_t0 [BATCH * T0LD];
__device__ float g_t1 [BATCH * 1024];
__device__ float g_t2 [BATCH * 1024];
__device__ float g_t3 [BATCH * 512];
__device__ float g_t4 [BATCH * 256];

// ---------------------------------------------------------------------------
// Generic SGEMM: C[M,N] = act(A[M,K] @ W[K,N] + bias), row-major, arbitrary lda.
// Block tile 128x128, BK=8, 256 threads, 8x8 per-thread tile.
// M is a multiple of 128 (grid.y), N a multiple of 128 (grid.x), K arbitrary.
// ---------------------------------------------------------------------------
__global__ __launch_bounds__(256)
void sgemm_bias_act(const float* __restrict__ A, int lda,
                    const float* __restrict__ W, int ldw,
                    const float* __restrict__ bias,
                    float* __restrict__ C, int ldc,
                    int K, int relu)
{
    __shared__ float As[8][128];   // As[k][m]
    __shared__ float Bs[8][128];   // Bs[k][n]

    const int tid  = threadIdx.x;
    const int brow = blockIdx.y << 7;
    const int bcol = blockIdx.x << 7;
    const int tr   = (tid >> 4) << 3;   // 0..120
    const int tc   = (tid & 15) << 3;   // 0..120

    // A load mapping: thread -> (m = tid/2, k = (tid&1)*4 + j), j=0..3
    const int am = tid >> 1;
    const int ak = (tid & 1) << 2;
    // W load mapping: thread -> (k = tid/32, n = (tid&31)*4), float4
    const int wk = tid >> 5;
    const int wn = (tid & 31) << 2;

    const float* Arow = A + (size_t)(brow + am) * lda;
    const float* Wp   = W + (size_t)wk * ldw + bcol + wn;

    float acc[8][8];
#pragma unroll
    for (int i = 0; i < 8; i++)
#pragma unroll
        for (int j = 0; j < 8; j++) acc[i][j] = 0.f;

    for (int k0 = 0; k0 < K; k0 += 8) {
#pragma unroll
        for (int j = 0; j < 4; j++) {
            int gk = k0 + ak + j;
            As[ak + j][am] = (gk < K) ? Arow[gk] : 0.f;
        }
        float4 wv;
        if (k0 + wk < K) wv = *(const float4*)(Wp + (size_t)k0 * ldw);
        else             wv = make_float4(0.f, 0.f, 0.f, 0.f);
        *(float4*)&Bs[wk][wn] = wv;

        __syncthreads();

#pragma unroll
        for (int k = 0; k < 8; k++) {
            float4 a0 = *(const float4*)&As[k][tr];
            float4 a1 = *(const float4*)&As[k][tr + 4];
            float4 b0 = *(const float4*)&Bs[k][tc];
            float4 b1 = *(const float4*)&Bs[k][tc + 4];
            float av[8] = {a0.x, a0.y, a0.z, a0.w, a1.x, a1.y, a1.z, a1.w};
            float bv[8] = {b0.x, b0.y, b0.z, b0.w, b1.x, b1.y, b1.z, b1.w};
#pragma unroll
            for (int i = 0; i < 8; i++)
#pragma unroll
                for (int j = 0; j < 8; j++)
                    acc[i][j] = fmaf(av[i], bv[j], acc[i][j]);
        }
        __syncthreads();
    }

    float bvals[8];
#pragma unroll
    for (int j = 0; j < 8; j++) bvals[j] = bias[bcol + tc + j];

#pragma unroll
    for (int i = 0; i < 8; i++) {
        float v[8];
#pragma unroll
        for (int j = 0; j < 8; j++) {
            float t = acc[i][j] + bvals[j];
            v[j] = relu ? fmaxf(t, 0.f) : t;
        }
        float* Cp = C + (size_t)(brow + tr + i) * ldc + bcol + tc;
        *(float4*)(Cp)     = make_float4(v[0], v[1], v[2], v[3]);
        *(float4*)(Cp + 4) = make_float4(v[4], v[5], v[6], v[7]);
    }
}

// ---------------------------------------------------------------------------
// Fused embedding gather + dot interaction.
// One warp per sample. feat[27][128] in smem (row 0 = bot_out, rows 1..26 =
// gathered embedding rows). Each lane < 28 computes a 4x4 tile of the 27x27
// Gram matrix (upper-triangular tiles only) with lane-staggered float4 smem
// reads (conflict-free). Writes t0[b] = [bot_out(128), triu(378), pad(6)].
// ---------------------------------------------------------------------------
__global__ __launch_bounds__(64)
void interact_kernel(const float* __restrict__ x,
                     const float* __restrict__ emb,
                     const float* __restrict__ bot,
                     float* __restrict__ t0)
{
    __shared__ float feat[2][NFEAT][EMBDIM];
    const int warp = threadIdx.x >> 5;
    const int lane = threadIdx.x & 31;
    const int b    = (blockIdx.x << 1) + warp;
    float (*f)[EMBDIM] = feat[warp];

    // gather bottom-MLP output row
    float4 botv = *(const float4*)(bot + (size_t)b * EMBDIM + lane * 4);
    *(float4*)&f[0][lane * 4] = botv;

    // categorical ids (exact: values < 2^24 stored in fp32)
    int myidx = 0;
    if (lane < NSPARSE) {
        float c = x[(size_t)b * XCOLS + NDENSE + lane];
        myidx = ((int)c) % VOCAB;
    }
    // gather 26 embedding rows, one 512B row per warp iteration (coalesced)
    for (int j = 0; j < NSPARSE; j++) {
        int row = __shfl_sync(0xffffffffu, myidx, j);
        *(float4*)&f[1 + j][lane * 4] =
            *(const float4*)(emb + (size_t)row * EMBDIM + lane * 4);
    }
    __syncwarp();

    // write bottom part of t0 + zero padding
    *(float4*)(t0 + (size_t)b * T0LD + lane * 4) = botv;
    if (lane < 6) t0[(size_t)b * T0LD + 506 + lane] = 0.f;

    if (lane < 28) {
        // map lane -> upper-triangular 4x4 tile (gi, gj), 7x7 tile grid
        int t = lane, gi = 0;
        while (t >= 7 - gi) { t -= 7 - gi; gi++; }
        int gj = gi + t;
        int i0 = gi << 2, j0 = gj << 2;

        float acc[4][4];
#pragma unroll
        for (int i = 0; i < 4; i++)
#pragma unroll
            for (int j = 0; j < 4; j++) acc[i][j] = 0.f;

#pragma unroll 4
        for (int c = 0; c < 32; c++) {
            int d = (((c + lane) & 31) << 2);   // lane-staggered chunk
            float4 ai[4], bj[4];
#pragma unroll
            for (int ii = 0; ii < 4; ii++)
                ai[ii] = (i0 + ii < NFEAT) ? *(const float4*)&f[i0 + ii][d]
                                           : make_float4(0.f, 0.f, 0.f, 0.f);
#pragma unroll
            for (int jj = 0; jj < 4; jj++)
                bj[jj] = (j0 + jj < NFEAT) ? *(const float4*)&f[j0 + jj][d]
                                           : make_float4(0.f, 0.f, 0.f, 0.f);
#pragma unroll
            for (int ii = 0; ii < 4; ii++)
#pragma unroll
                for (int jj = 0; jj < 4; jj++) {
                    acc[ii][jj] = fmaf(ai[ii].x, bj[jj].x, acc[ii][jj]);
                    acc[ii][jj] = fmaf(ai[ii].y, bj[jj].y, acc[ii][jj]);
                    acc[ii][jj] = fmaf(ai[ii].z, bj[jj].z, acc[ii][jj]);
                    acc[ii][jj] = fmaf(ai[ii].w, bj[jj].w, acc[ii][jj]);
                }
        }

        // scatter into triu(27) ordering: offset(i,j) = i*27 - i(i-1)/2 + (j-i)
        float* outp = t0 + (size_t)b * T0LD + EMBDIM;
#pragma unroll
        for (int ii = 0; ii < 4; ii++)
#pragma unroll
            for (int jj = 0; jj < 4; jj++) {
                int i = i0 + ii, j = j0 + jj;
                if (i < NFEAT && j < NFEAT && i <= j) {
                    int off = i * NFEAT - ((i * (i - 1)) >> 1) + (j - i);
                    outp[off] = acc[ii][jj];
                }
            }
    }
}

// ---------------------------------------------------------------------------
// Final layer: out[b] = t4[b,:] @ w[256,1] + bias.  One warp per row.
// ---------------------------------------------------------------------------
__global__ __launch_bounds__(256)
void final_layer(const float* __restrict__ t4,
                 const float* __restrict__ w,
                 const float* __restrict__ bias,
                 float* __restrict__ out)
{
    const int warp = threadIdx.x >> 5;
    const int lane = threadIdx.x & 31;
    const int row  = (blockIdx.x << 3) + warp;

    float s = 0.f;
#pragma unroll
    for (int k = lane; k < 256; k += 32)
        s = fmaf(t4[(size_t)row * 256 + k], __ldg(&w[k]), s);
#pragma unroll
    for (int o = 16; o; o >>= 1)
        s += __shfl_down_sync(0xffffffffu, s, o);
    if (lane == 0) out[row] = s + bias[0];
}

// ---------------------------------------------------------------------------
extern "C" void kernel_launch(void* const* d_in, const int* in_sizes, int n_in,
                              void* d_out, int out_size)
{
    (void)in_sizes; (void)n_in; (void)out_size;

    const float* x   = (const float*)d_in[0];
    // d_in[1] = train flag (unused)
    const float* bw0 = (const float*)d_in[2];
    const float* bb0 = (const float*)d_in[3];
    const float* bw1 = (const float*)d_in[4];
    const float* bb1 = (const float*)d_in[5];
    const float* bw2 = (const float*)d_in[6];
    const float* bb2 = (const float*)d_in[7];
    const float* emb = (const float*)d_in[8];
    const float* tw0 = (const float*)d_in[9];
    const float* tb0 = (const float*)d_in[10];
    const float* tw1 = (const float*)d_in[11];
    const float* tb1 = (const float*)d_in[12];
    const float* tw2 = (const float*)d_in[13];
    const float* tb2 = (const float*)d_in[14];
    const float* tw3 = (const float*)d_in[15];
    const float* tb3 = (const float*)d_in[16];
    const float* tw4 = (const float*)d_in[17];
    const float* tb4 = (const float*)d_in[18];
    float* out = (float*)d_out;

    float *h1, *h2, *bot, *t0, *t1, *t2, *t3, *t4;
    cudaGetSymbolAddress((void**)&h1,  g_h1);
    cudaGetSymbolAddress((void**)&h2,  g_h2);
    cudaGetSymbolAddress((void**)&bot, g_bot);
    cudaGetSymbolAddress((void**)&t0,  g_t0);
    cudaGetSymbolAddress((void**)&t1,  g_t1);
    cudaGetSymbolAddress((void**)&t2,  g_t2);
    cudaGetSymbolAddress((void**)&t3,  g_t3);
    cudaGetSymbolAddress((void**)&t4,  g_t4);

    const int MB = BATCH / 128;  // 128 row-blocks

    // bottom MLP: 13 -> 512 -> 256 -> 128 (relu)
    sgemm_bias_act<<<dim3(4, MB), 256>>>(x,  XCOLS, bw0, 512, bb0, h1,  512, 13,  1);
    sgemm_bias_act<<<dim3(2, MB), 256>>>(h1, 512,   bw1, 256, bb1, h2,  256, 512, 1);
    sgemm_bias_act<<<dim3(1, MB), 256>>>(h2, 256,   bw2, 128, bb2, bot, 128, 256, 1);

    // gather + interaction -> t0 [B, 506] (stride 512)
    interact_kernel<<<BATCH / 2, 64>>>(x, emb, bot, t0);

    // top MLP: 506 -> 1024 -> 1024 -> 512 -> 256 (relu)
    sgemm_bias_act<<<dim3(8, MB), 256>>>(t0, T0LD, tw0, 1024, tb0, t1, 1024, 506,  1);
    sgemm_bias_act<<<dim3(8, MB), 256>>>(t1, 1024, tw1, 1024, tb1, t2, 1024, 1024, 1);
    sgemm_bias_act<<<dim3(4, MB), 256>>>(t2, 1024, tw2, 512,  tb2, t3, 512,  1024, 1);
    sgemm_bias_act<<<dim3(2, MB), 256>>>(t3, 512,  tw3, 256,  tb3, t4, 256,  512,  1);

    // final: 256 -> 1 (no relu)
    final_layer<<<BATCH / 8, 256>>>(t4, tw4, tb4, out);
}

// round 5
// speedup vs baseline: 1.4787x; 1.4787x over previous
#include <cuda_runtime.h>
#include <cuda_bf16.h>
#include <cstdio>

// ---------------------------------------------------------------------------
// DLRM forward. GEMMs via mma.sync tf32 (3xTF32 split -> fp32-level accuracy).
//   x [16384,39] = 13 dense + 26 categorical (float-encoded ids)
//   bottom MLP 13->512->256->128 (relu)
//   feat = [bot_out ; emb[idx]] -> [B,27,128]; inter = triu(f f^T) -> [B,378]
//   t0 = [bot_out, inter] -> [B,506]  (stored with stride 512)
//   top MLP 506->1024->1024->512->256->1 (relu except last)
// ---------------------------------------------------------------------------

#define BATCH   16384
#define NDENSE  13
#define NSPARSE 26
#define XCOLS   39
#define EMBDIM  128
#define VOCAB   1000000
#define NFEAT   27
#define T0LD    512

// -------------------- scratch (device globals; no allocation) --------------
__device__ float g_h1 [BATCH * 512];
__device__ float g_h2 [BATCH * 256];
__device__ float g_bot[BATCH * 128];
__device__ float g_t0 [BATCH * T0LD];
__device__ float g_t1 [BATCH * 1024];
__device__ float g_t2 [BATCH * 1024];
__device__ float g_t3 [BATCH * 512];
__device__ float g_t4 [BATCH * 256];

// ---------------------------------------------------------------------------
// tf32 helpers
// ---------------------------------------------------------------------------
__device__ __forceinline__ float tf32_round(float x) {
    unsigned u;
    asm("cvt.rna.tf32.f32 %0, %1;" : "=r"(u) : "f"(x));
    return __uint_as_float(u);
}
__device__ __forceinline__ void split_tf32(float x, float& hi, float& lo) {
    hi = tf32_round(x);
    lo = tf32_round(x - hi);
}
// D(+)= A(16x8,row) * B(8x8,col-frag) ; tf32 inputs, fp32 accum
__device__ __forceinline__ void mma8(float* c, const unsigned* a, const unsigned* b) {
    asm volatile(
        "mma.sync.aligned.m16n8k8.row.col.f32.tf32.tf32.f32 "
        "{%0,%1,%2,%3}, {%4,%5,%6,%7}, {%8,%9}, {%0,%1,%2,%3};\n"
        : "+f"(c[0]), "+f"(c[1]), "+f"(c[2]), "+f"(c[3])
        : "r"(a[0]), "r"(a[1]), "r"(a[2]), "r"(a[3]), "r"(b[0]), "r"(b[1]));
}

// ---------------------------------------------------------------------------
// Tensor-core GEMM: C[M,N] = act(A[M,K] @ W[K,N] + bias), row-major.
// Block tile 128(M) x 128(N), BK=16, 256 threads (8 warps, 4x2 warp grid,
// warp tile 32x64). 3xTF32: hi/lo split done once at smem-store time.
// M,N multiples of 128; K arbitrary (zero-filled).
// ---------------------------------------------------------------------------
__global__ __launch_bounds__(256)
void gemm_tf32(const float* __restrict__ A, int lda,
               const float* __restrict__ W, int ldw,
               const float* __restrict__ bias,
               float* __restrict__ C, int ldc,
               int K, int relu)
{
    // strides chosen so all fragment LDS are bank-conflict-free
    __shared__ float As_hi[128][20], As_lo[128][20];   // [m][k], k-pad 16->20
    __shared__ float Bs_hi[16][136], Bs_lo[16][136];   // [k][n], n-pad 128->136

    const int tid  = threadIdx.x;
    const int brow = blockIdx.y << 7;
    const int bcol = blockIdx.x << 7;
    const int warp = tid >> 5;
    const int lane = tid & 31;
    const int g    = lane >> 2;       // groupID 0..7
    const int tg   = lane & 3;        // thread-in-group 0..3
    const int wm   = (warp & 3) << 5; // warp m-offset: 0,32,64,96
    const int wn   = (warp >> 2) << 6;// warp n-offset: 0,64

    float acc[2][8][4];
#pragma unroll
    for (int mi = 0; mi < 2; mi++)
#pragma unroll
        for (int nj = 0; nj < 8; nj++)
#pragma unroll
            for (int q = 0; q < 4; q++) acc[mi][nj][q] = 0.f;

    for (int k0 = 0; k0 < K; k0 += 16) {
        // ---- stage A tile [128x16] (scalar loads; lda may be odd) ----
#pragma unroll
        for (int i = 0; i < 2; i++) {
            int f   = tid + (i << 8);
            int row = f >> 2;
            int kq  = (f & 3) << 2;
            const float* Ap = A + (size_t)(brow + row) * lda + k0 + kq;
            float4 hv, lv;
            float v;
            v = (k0 + kq + 0 < K) ? Ap[0] : 0.f; split_tf32(v, hv.x, lv.x);
            v = (k0 + kq + 1 < K) ? Ap[1] : 0.f; split_tf32(v, hv.y, lv.y);
            v = (k0 + kq + 2 < K) ? Ap[2] : 0.f; split_tf32(v, hv.z, lv.z);
            v = (k0 + kq + 3 < K) ? Ap[3] : 0.f; split_tf32(v, hv.w, lv.w);
            *(float4*)&As_hi[row][kq] = hv;
            *(float4*)&As_lo[row][kq] = lv;
        }
        // ---- stage B tile [16x128] (vector loads; ldw multiple of 4) ----
#pragma unroll
        for (int i = 0; i < 2; i++) {
            int f  = tid + (i << 8);
            int kk = f >> 5;
            int nq = (f & 31) << 2;
            float4 wv = (k0 + kk < K)
                ? *(const float4*)(W + (size_t)(k0 + kk) * ldw + bcol + nq)
                : make_float4(0.f, 0.f, 0.f, 0.f);
            float4 hv, lv;
            split_tf32(wv.x, hv.x, lv.x);
            split_tf32(wv.y, hv.y, lv.y);
            split_tf32(wv.z, hv.z, lv.z);
            split_tf32(wv.w, hv.w, lv.w);
            *(float4*)&Bs_hi[kk][nq] = hv;
            *(float4*)&Bs_lo[kk][nq] = lv;
        }
        __syncthreads();

#pragma unroll
        for (int ks = 0; ks < 2; ks++) {
            const int kf = ks << 3;
            // A fragments (2 x m16k8), hi & lo
            unsigned ahi[2][4], alo[2][4];
#pragma unroll
            for (int mi = 0; mi < 2; mi++) {
                int mb = wm + (mi << 4);
                ahi[mi][0] = __float_as_uint(As_hi[mb + g    ][kf + tg    ]);
                ahi[mi][1] = __float_as_uint(As_hi[mb + g + 8][kf + tg    ]);
                ahi[mi][2] = __float_as_uint(As_hi[mb + g    ][kf + tg + 4]);
                ahi[mi][3] = __float_as_uint(As_hi[mb + g + 8][kf + tg + 4]);
                alo[mi][0] = __float_as_uint(As_lo[mb + g    ][kf + tg    ]);
                alo[mi][1] = __float_as_uint(As_lo[mb + g + 8][kf + tg    ]);
                alo[mi][2] = __float_as_uint(As_lo[mb + g    ][kf + tg + 4]);
                alo[mi][3] = __float_as_uint(As_lo[mb + g + 8][kf + tg + 4]);
            }
#pragma unroll
            for (int nj = 0; nj < 8; nj++) {
                int nb = wn + (nj << 3);
                unsigned bh[2], bl[2];
                bh[0] = __float_as_uint(Bs_hi[kf + tg    ][nb + g]);
                bh[1] = __float_as_uint(Bs_hi[kf + tg + 4][nb + g]);
                bl[0] = __float_as_uint(Bs_lo[kf + tg    ][nb + g]);
                bl[1] = __float_as_uint(Bs_lo[kf + tg + 4][nb + g]);
#pragma unroll
                for (int mi = 0; mi < 2; mi++) {
                    mma8(acc[mi][nj], ahi[mi], bh);   // hi*hi
                    mma8(acc[mi][nj], alo[mi], bh);   // lo*hi
                    mma8(acc[mi][nj], ahi[mi], bl);   // hi*lo
                }
            }
        }
        __syncthreads();
    }

    // ---- epilogue: bias + relu, float2 stores ----
#pragma unroll
    for (int nj = 0; nj < 8; nj++) {
        int col = bcol + wn + (nj << 3) + (tg << 1);
        float b0 = bias[col], b1 = bias[col + 1];
#pragma unroll
        for (int mi = 0; mi < 2; mi++) {
            int r0 = brow + wm + (mi << 4) + g;
            float v0 = acc[mi][nj][0] + b0;
            float v1 = acc[mi][nj][1] + b1;
            float v2 = acc[mi][nj][2] + b0;
            float v3 = acc[mi][nj][3] + b1;
            if (relu) {
                v0 = fmaxf(v0, 0.f); v1 = fmaxf(v1, 0.f);
                v2 = fmaxf(v2, 0.f); v3 = fmaxf(v3, 0.f);
            }
            *(float2*)(C + (size_t)r0 * ldc + col)       = make_float2(v0, v1);
            *(float2*)(C + (size_t)(r0 + 8) * ldc + col) = make_float2(v2, v3);
        }
    }
}

// ---------------------------------------------------------------------------
// Fused embedding gather + dot interaction (one warp per sample).
// ---------------------------------------------------------------------------
__global__ __launch_bounds__(64)
void interact_kernel(const float* __restrict__ x,
                     const float* __restrict__ emb,
                     const float* __restrict__ bot,
                     float* __restrict__ t0)
{
    __shared__ float feat[2][NFEAT][EMBDIM];
    const int warp = threadIdx.x >> 5;
    const int lane = threadIdx.x & 31;
    const int b    = (blockIdx.x << 1) + warp;
    float (*f)[EMBDIM] = feat[warp];

    float4 botv = *(const float4*)(bot + (size_t)b * EMBDIM + lane * 4);
    *(float4*)&f[0][lane * 4] = botv;

    int myidx = 0;
    if (lane < NSPARSE) {
        float c = x[(size_t)b * XCOLS + NDENSE + lane];
        myidx = ((int)c) % VOCAB;
    }
    for (int j = 0; j < NSPARSE; j++) {
        int row = __shfl_sync(0xffffffffu, myidx, j);
        *(float4*)&f[1 + j][lane * 4] =
            *(const float4*)(emb + (size_t)row * EMBDIM + lane * 4);
    }
    __syncwarp();

    *(float4*)(t0 + (size_t)b * T0LD + lane * 4) = botv;
    if (lane < 6) t0[(size_t)b * T0LD + 506 + lane] = 0.f;

    if (lane < 28) {
        int t = lane, gi = 0;
        while (t >= 7 - gi) { t -= 7 - gi; gi++; }
        int gj = gi + t;
        int i0 = gi << 2, j0 = gj << 2;

        float acc[4][4];
#pragma unroll
        for (int i = 0; i < 4; i++)
#pragma unroll
            for (int j = 0; j < 4; j++) acc[i][j] = 0.f;

#pragma unroll 4
        for (int c = 0; c < 32; c++) {
            int d = (((c + lane) & 31) << 2);
            float4 ai[4], bj[4];
#pragma unroll
            for (int ii = 0; ii < 4; ii++)
                ai[ii] = (i0 + ii < NFEAT) ? *(const float4*)&f[i0 + ii][d]
                                           : make_float4(0.f, 0.f, 0.f, 0.f);
#pragma unroll
            for (int jj = 0; jj < 4; jj++)
                bj[jj] = (j0 + jj < NFEAT) ? *(const float4*)&f[j0 + jj][d]
                                           : make_float4(0.f, 0.f, 0.f, 0.f);
#pragma unroll
            for (int ii = 0; ii < 4; ii++)
#pragma unroll
                for (int jj = 0; jj < 4; jj++) {
                    acc[ii][jj] = fmaf(ai[ii].x, bj[jj].x, acc[ii][jj]);
                    acc[ii][jj] = fmaf(ai[ii].y, bj[jj].y, acc[ii][jj]);
                    acc[ii][jj] = fmaf(ai[ii].z, bj[jj].z, acc[ii][jj]);
                    acc[ii][jj] = fmaf(ai[ii].w, bj[jj].w, acc[ii][jj]);
                }
        }

        float* outp = t0 + (size_t)b * T0LD + EMBDIM;
#pragma unroll
        for (int ii = 0; ii < 4; ii++)
#pragma unroll
            for (int jj = 0; jj < 4; jj++) {
                int i = i0 + ii, j = j0 + jj;
                if (i < NFEAT && j < NFEAT && i <= j) {
                    int off = i * NFEAT - ((i * (i - 1)) >> 1) + (j - i);
                    outp[off] = acc[ii][jj];
                }
            }
    }
}

// ---------------------------------------------------------------------------
// Final layer: out[b] = t4[b,:] @ w[256,1] + bias. One warp per row.
// ---------------------------------------------------------------------------
__global__ __launch_bounds__(256)
void final_layer(const float* __restrict__ t4,
                 const float* __restrict__ w,
                 const float* __restrict__ bias,
                 float* __restrict__ out)
{
    const int warp = threadIdx.x >> 5;
    const int lane = threadIdx.x & 31;
    const int row  = (blockIdx.x << 3) + warp;

    float s = 0.f;
#pragma unroll
    for (int k = lane; k < 256; k += 32)
        s = fmaf(t4[(size_t)row * 256 + k], __ldg(&w[k]), s);
#pragma unroll
    for (int o = 16; o; o >>= 1)
        s += __shfl_down_sync(0xffffffffu, s, o);
    if (lane == 0) out[row] = s + bias[0];
}

// ---------------------------------------------------------------------------
extern "C" void kernel_launch(void* const* d_in, const int* in_sizes, int n_in,
                              void* d_out, int out_size)
{
    (void)in_sizes; (void)n_in; (void)out_size;

    const float* x   = (const float*)d_in[0];
    const float* bw0 = (const float*)d_in[2];
    const float* bb0 = (const float*)d_in[3];
    const float* bw1 = (const float*)d_in[4];
    const float* bb1 = (const float*)d_in[5];
    const float* bw2 = (const float*)d_in[6];
    const float* bb2 = (const float*)d_in[7];
    const float* emb = (const float*)d_in[8];
    const float* tw0 = (const float*)d_in[9];
    const float* tb0 = (const float*)d_in[10];
    const float* tw1 = (const float*)d_in[11];
    const float* tb1 = (const float*)d_in[12];
    const float* tw2 = (const float*)d_in[13];
    const float* tb2 = (const float*)d_in[14];
    const float* tw3 = (const float*)d_in[15];
    const float* tb3 = (const float*)d_in[16];
    const float* tw4 = (const float*)d_in[17];
    const float* tb4 = (const float*)d_in[18];
    float* out = (float*)d_out;

    float *h1, *h2, *bot, *t0, *t1, *t2, *t3, *t4;
    cudaGetSymbolAddress((void**)&h1,  g_h1);
    cudaGetSymbolAddress((void**)&h2,  g_h2);
    cudaGetSymbolAddress((void**)&bot, g_bot);
    cudaGetSymbolAddress((void**)&t0,  g_t0);
    cudaGetSymbolAddress((void**)&t1,  g_t1);
    cudaGetSymbolAddress((void**)&t2,  g_t2);
    cudaGetSymbolAddress((void**)&t3,  g_t3);
    cudaGetSymbolAddress((void**)&t4,  g_t4);

    const int MB = BATCH / 128;

    // bottom MLP: 13 -> 512 -> 256 -> 128 (relu)
    gemm_tf32<<<dim3(4, MB), 256>>>(x,  XCOLS, bw0, 512, bb0, h1,  512, 13,  1);
    gemm_tf32<<<dim3(2, MB), 256>>>(h1, 512,   bw1, 256, bb1, h2,  256, 512, 1);
    gemm_tf32<<<dim3(1, MB), 256>>>(h2, 256,   bw2, 128, bb2, bot, 128, 256, 1);

    // gather + interaction -> t0 [B, 506] (stride 512)
    interact_kernel<<<BATCH / 2, 64>>>(x, emb, bot, t0);

    // top MLP: 506 -> 1024 -> 1024 -> 512 -> 256 (relu)
    gemm_tf32<<<dim3(8, MB), 256>>>(t0, T0LD, tw0, 1024, tb0, t1, 1024, 506,  1);
    gemm_tf32<<<dim3(8, MB), 256>>>(t1, 1024, tw1, 1024, tb1, t2, 1024, 1024, 1);
    gemm_tf32<<<dim3(4, MB), 256>>>(t2, 1024, tw2, 512,  tb2, t3, 512,  1024, 1);
    gemm_tf32<<<dim3(2, MB), 256>>>(t3, 512,  tw3, 256,  tb3, t4, 256,  512,  1);

    // final: 256 -> 1 (no relu)
    final_layer<<<BATCH / 8, 256>>>(t4, tw4, tb4, out);
}

// round 6
// speedup vs baseline: 2.9323x; 1.9830x over previous
#include <cuda_runtime.h>
#include <cuda_fp16.h>
#include <cstdio>
#include <cstdint>

// ---------------------------------------------------------------------------
// DLRM forward. GEMMs via mma.sync.m16n8k16.f16 with 3-term fp16 split
// (hi*hi + lo*hi + hi*lo), fp32 accumulate -> ~tf32x3 accuracy, half the MMAs.
// All operands pre-split into packed (hi,lo) fp16 u32 words once per launch.
// ---------------------------------------------------------------------------

#define BATCH   16384
#define NDENSE  13
#define NSPARSE 26
#define XCOLS   39
#define EMBDIM  128
#define VOCAB   1000000
#define NFEAT   27
#define T0LD    512

// -------------------- scratch (device globals; no allocation) --------------
// packed activations (u32 = hi f16 | lo f16 << 16)
__device__ uint32_t g_a0 [BATCH * 16];     // x dense cols, K padded 13->16
__device__ uint32_t g_h1 [BATCH * 512];
__device__ uint32_t g_h2 [BATCH * 256];
__device__ float    g_bot[BATCH * 128];    // fp32 (consumed by interact)
__device__ uint32_t g_t0 [BATCH * T0LD];
__device__ uint32_t g_t1 [BATCH * 1024];
__device__ uint32_t g_t2 [BATCH * 1024];
__device__ uint32_t g_t3 [BATCH * 512];
__device__ uint32_t g_t4 [BATCH * 256];
// packed weights [Kpad][N]
__device__ uint32_t g_w0p [16   * 512];
__device__ uint32_t g_w1p [512  * 256];
__device__ uint32_t g_w2p [256  * 128];
__device__ uint32_t g_tw0p[512  * 1024];   // 506 -> 512 zero-padded rows
__device__ uint32_t g_tw1p[1024 * 1024];
__device__ uint32_t g_tw2p[1024 * 512];
__device__ uint32_t g_tw3p[512  * 256];

// ---------------------------------------------------------------------------
__device__ __forceinline__ uint32_t pack_hl(float v) {
    __half h = __float2half_rn(v);
    float  r = v - __half2float(h);
    __half l = __float2half_rn(r);
    return (uint32_t)__half_as_ushort(h) | ((uint32_t)__half_as_ushort(l) << 16);
}

// D(+)= A(16x16) * B(16x8); f16 in, f32 accum
__device__ __forceinline__ void mma16(float* c, const uint32_t* a,
                                      uint32_t b0, uint32_t b1) {
    asm volatile(
        "mma.sync.aligned.m16n8k16.row.col.f32.f16.f16.f32 "
        "{%0,%1,%2,%3}, {%4,%5,%6,%7}, {%8,%9}, {%0,%1,%2,%3};\n"
        : "+f"(c[0]), "+f"(c[1]), "+f"(c[2]), "+f"(c[3])
        : "r"(a[0]), "r"(a[1]), "r"(a[2]), "r"(a[3]), "r"(b0), "r"(b1));
}

__device__ __forceinline__ void ldsm4t(uint32_t* r, uint32_t addr) {
    asm volatile(
        "ldmatrix.sync.aligned.m8n8.x4.trans.shared.b16 {%0,%1,%2,%3}, [%4];\n"
        : "=r"(r[0]), "=r"(r[1]), "=r"(r[2]), "=r"(r[3]) : "r"(addr));
}

// ---------------------------------------------------------------------------
// Prepass: split fp32 -> packed (hi,lo) f16, with K zero-padding.
// out[k][n] for k<K = pack(in[k][n]); k in [K,Kpad) = 0.
// ---------------------------------------------------------------------------
__global__ void conv_pack(const float* __restrict__ in, uint32_t* __restrict__ out,
                          int K, int Kpad, int N)
{
    int i = blockIdx.x * blockDim.x + threadIdx.x;
    int total = Kpad * N;
    if (i >= total) return;
    int k = i / N, n = i - k * N;
    out[i] = (k < K) ? pack_hl(in[(size_t)k * N + n]) : 0u;
}

// x [B,39] -> a0 [B,16] packed (first 13 cols, rest 0)
__global__ void conv_x(const float* __restrict__ x, uint32_t* __restrict__ a0)
{
    int i = blockIdx.x * blockDim.x + threadIdx.x;   // B*16
    if (i >= BATCH * 16) return;
    int b = i >> 4, k = i & 15;
    a0[i] = (k < NDENSE) ? pack_hl(x[(size_t)b * XCOLS + k]) : 0u;
}

// ---------------------------------------------------------------------------
// GEMM: C[M,N] = act(A @ W + bias). A,W packed (hi,lo) f16. K multiple of 16.
// Block 128x128, 256 thr, 8 warps (4x2), warp tile 32x64, BK=16.
// ---------------------------------------------------------------------------
#define ASTRIDE 12   // words per A smem row (16 halves used, pad->24)
#define BSTRIDE 68   // words per B smem k-row (128 halves used, pad->136)

__global__ __launch_bounds__(256, 2)
void gemm_hl(const uint32_t* __restrict__ A, int lda,
             const uint32_t* __restrict__ W, int ldw,
             const float* __restrict__ bias,
             void* __restrict__ Cv, int ldc,
             int K, int relu, int pack_out)
{
    __shared__ uint32_t As_hi[128 * ASTRIDE], As_lo[128 * ASTRIDE];
    __shared__ uint32_t Bs_hi[16 * BSTRIDE],  Bs_lo[16 * BSTRIDE];

    const int tid  = threadIdx.x;
    const int brow = blockIdx.y << 7;
    const int bcol = blockIdx.x << 7;
    const int warp = tid >> 5;
    const int lane = tid & 31;
    const int g    = lane >> 2;
    const int tg   = lane & 3;
    const int wm   = (warp & 3) << 5;
    const int wn   = (warp >> 2) << 6;

    // ldmatrix.x4.trans lane address into Bs (byte addr), per 16-col group
    const int mi_  = lane >> 3;
    const int r_   = lane & 7;
    const int kr   = ((mi_ & 1) << 3) + r_;
    const int noff = (mi_ >> 1) << 3;
    const uint32_t bhi_base =
        (uint32_t)__cvta_generic_to_shared(Bs_hi) +
        (uint32_t)(kr * BSTRIDE + ((wn + noff) >> 1)) * 4u;
    const uint32_t blo_base =
        (uint32_t)__cvta_generic_to_shared(Bs_lo) +
        (uint32_t)(kr * BSTRIDE + ((wn + noff) >> 1)) * 4u;

    float acc[2][8][4];
#pragma unroll
    for (int mi = 0; mi < 2; mi++)
#pragma unroll
        for (int nj = 0; nj < 8; nj++)
#pragma unroll
            for (int q = 0; q < 4; q++) acc[mi][nj][q] = 0.f;

    for (int k0 = 0; k0 < K; k0 += 16) {
        // ---- stage A [128 rows x 16 k] ----
#pragma unroll
        for (int i = 0; i < 2; i++) {
            int f   = tid + (i << 8);
            int row = f >> 2;
            int q   = f & 3;
            uint4 w = *(const uint4*)(A + (size_t)(brow + row) * lda + k0 + (q << 2));
            uint32_t hi01 = __byte_perm(w.x, w.y, 0x5410);
            uint32_t lo01 = __byte_perm(w.x, w.y, 0x7632);
            uint32_t hi23 = __byte_perm(w.z, w.w, 0x5410);
            uint32_t lo23 = __byte_perm(w.z, w.w, 0x7632);
            int idx = row * ASTRIDE + (q << 1);
            *(uint2*)&As_hi[idx] = make_uint2(hi01, hi23);
            *(uint2*)&As_lo[idx] = make_uint2(lo01, lo23);
        }
        // ---- stage B [16 k x 128 n] ----
#pragma unroll
        for (int i = 0; i < 2; i++) {
            int f  = tid + (i << 8);
            int kk = f >> 5;
            int n4 = (f & 31) << 2;
            uint4 w = *(const uint4*)(W + (size_t)(k0 + kk) * ldw + bcol + n4);
            uint32_t hi01 = __byte_perm(w.x, w.y, 0x5410);
            uint32_t lo01 = __byte_perm(w.x, w.y, 0x7632);
            uint32_t hi23 = __byte_perm(w.z, w.w, 0x5410);
            uint32_t lo23 = __byte_perm(w.z, w.w, 0x7632);
            int idx = kk * BSTRIDE + (n4 >> 1);
            *(uint2*)&Bs_hi[idx] = make_uint2(hi01, hi23);
            *(uint2*)&Bs_lo[idx] = make_uint2(lo01, lo23);
        }
        __syncthreads();

        // ---- A fragments (2 x m16k16), hi & lo ----
        uint32_t ah[2][4], al[2][4];
#pragma unroll
        for (int mi = 0; mi < 2; mi++) {
            int r0 = (wm + (mi << 4) + g) * ASTRIDE;
            int r1 = (wm + (mi << 4) + g + 8) * ASTRIDE;
            ah[mi][0] = As_hi[r0 + tg];     ah[mi][1] = As_hi[r1 + tg];
            ah[mi][2] = As_hi[r0 + tg + 4]; ah[mi][3] = As_hi[r1 + tg + 4];
            al[mi][0] = As_lo[r0 + tg];     al[mi][1] = As_lo[r1 + tg];
            al[mi][2] = As_lo[r0 + tg + 4]; al[mi][3] = As_lo[r1 + tg + 4];
        }

#pragma unroll
        for (int njp = 0; njp < 4; njp++) {
            uint32_t bh[4], bl[4];
            ldsm4t(bh, bhi_base + njp * 32u);
            ldsm4t(bl, blo_base + njp * 32u);
#pragma unroll
            for (int s = 0; s < 2; s++) {
                int nj = (njp << 1) + s;
#pragma unroll
                for (int mi = 0; mi < 2; mi++) {
                    mma16(acc[mi][nj], ah[mi], bh[2*s], bh[2*s+1]);  // hi*hi
                    mma16(acc[mi][nj], al[mi], bh[2*s], bh[2*s+1]);  // lo*hi
                    mma16(acc[mi][nj], ah[mi], bl[2*s], bl[2*s+1]);  // hi*lo
                }
            }
        }
        __syncthreads();
    }

    // ---- epilogue ----
#pragma unroll
    for (int nj = 0; nj < 8; nj++) {
        int col = bcol + wn + (nj << 3) + (tg << 1);
        float b0 = bias[col], b1 = bias[col + 1];
#pragma unroll
        for (int mi = 0; mi < 2; mi++) {
            int r0 = brow + wm + (mi << 4) + g;
            float v0 = acc[mi][nj][0] + b0;
            float v1 = acc[mi][nj][1] + b1;
            float v2 = acc[mi][nj][2] + b0;
            float v3 = acc[mi][nj][3] + b1;
            if (relu) {
                v0 = fmaxf(v0, 0.f); v1 = fmaxf(v1, 0.f);
                v2 = fmaxf(v2, 0.f); v3 = fmaxf(v3, 0.f);
            }
            if (pack_out) {
                uint32_t* C = (uint32_t*)Cv;
                *(uint2*)(C + (size_t)r0 * ldc + col) =
                    make_uint2(pack_hl(v0), pack_hl(v1));
                *(uint2*)(C + (size_t)(r0 + 8) * ldc + col) =
                    make_uint2(pack_hl(v2), pack_hl(v3));
            } else {
                float* C = (float*)Cv;
                *(float2*)(C + (size_t)r0 * ldc + col)       = make_float2(v0, v1);
                *(float2*)(C + (size_t)(r0 + 8) * ldc + col) = make_float2(v2, v3);
            }
        }
    }
}

// ---------------------------------------------------------------------------
// Fused embedding gather + dot interaction (one warp per sample).
// Writes t0 PACKED: [pack(bot)(128), pack(triu)(378), 0-pad(6)].
// ---------------------------------------------------------------------------
__global__ __launch_bounds__(64)
void interact_kernel(const float* __restrict__ x,
                     const float* __restrict__ emb,
                     const float* __restrict__ bot,
                     uint32_t* __restrict__ t0)
{
    __shared__ float feat[2][NFEAT][EMBDIM];
    const int warp = threadIdx.x >> 5;
    const int lane = threadIdx.x & 31;
    const int b    = (blockIdx.x << 1) + warp;
    float (*f)[EMBDIM] = feat[warp];

    float4 botv = *(const float4*)(bot + (size_t)b * EMBDIM + lane * 4);
    *(float4*)&f[0][lane * 4] = botv;

    int myidx = 0;
    if (lane < NSPARSE) {
        float c = x[(size_t)b * XCOLS + NDENSE + lane];
        myidx = ((int)c) % VOCAB;
    }
    for (int j = 0; j < NSPARSE; j++) {
        int row = __shfl_sync(0xffffffffu, myidx, j);
        *(float4*)&f[1 + j][lane * 4] =
            *(const float4*)(emb + (size_t)row * EMBDIM + lane * 4);
    }
    __syncwarp();

    // packed bottom part + zero padding
    uint4 pw = make_uint4(pack_hl(botv.x), pack_hl(botv.y),
                          pack_hl(botv.z), pack_hl(botv.w));
    *(uint4*)(t0 + (size_t)b * T0LD + lane * 4) = pw;
    if (lane < 6) t0[(size_t)b * T0LD + 506 + lane] = 0u;

    if (lane < 28) {
        int t = lane, gi = 0;
        while (t >= 7 - gi) { t -= 7 - gi; gi++; }
        int gj = gi + t;
        int i0 = gi << 2, j0 = gj << 2;

        float acc[4][4];
#pragma unroll
        for (int i = 0; i < 4; i++)
#pragma unroll
            for (int j = 0; j < 4; j++) acc[i][j] = 0.f;

#pragma unroll 4
        for (int c = 0; c < 32; c++) {
            int d = (((c + lane) & 31) << 2);
            float4 ai[4], bj[4];
#pragma unroll
            for (int ii = 0; ii < 4; ii++)
                ai[ii] = (i0 + ii < NFEAT) ? *(const float4*)&f[i0 + ii][d]
                                           : make_float4(0.f, 0.f, 0.f, 0.f);
#pragma unroll
            for (int jj = 0; jj < 4; jj++)
                bj[jj] = (j0 + jj < NFEAT) ? *(const float4*)&f[j0 + jj][d]
                                           : make_float4(0.f, 0.f, 0.f, 0.f);
#pragma unroll
            for (int ii = 0; ii < 4; ii++)
#pragma unroll
                for (int jj = 0; jj < 4; jj++) {
                    acc[ii][jj] = fmaf(ai[ii].x, bj[jj].x, acc[ii][jj]);
                    acc[ii][jj] = fmaf(ai[ii].y, bj[jj].y, acc[ii][jj]);
                    acc[ii][jj] = fmaf(ai[ii].z, bj[jj].z, acc[ii][jj]);
                    acc[ii][jj] = fmaf(ai[ii].w, bj[jj].w, acc[ii][jj]);
                }
        }

        uint32_t* outp = t0 + (size_t)b * T0LD + EMBDIM;
#pragma unroll
        for (int ii = 0; ii < 4; ii++)
#pragma unroll
            for (int jj = 0; jj < 4; jj++) {
                int i = i0 + ii, j = j0 + jj;
                if (i < NFEAT && j < NFEAT && i <= j) {
                    int off = i * NFEAT - ((i * (i - 1)) >> 1) + (j - i);
                    outp[off] = pack_hl(acc[ii][jj]);
                }
            }
    }
}

// ---------------------------------------------------------------------------
// Final layer: out[b] = t4[b,:] @ w[256,1] + bias. t4 packed. One warp/row.
// ---------------------------------------------------------------------------
__global__ __launch_bounds__(256)
void final_layer(const uint32_t* __restrict__ t4,
                 const float* __restrict__ w,
                 const float* __restrict__ bias,
                 float* __restrict__ out)
{
    const int warp = threadIdx.x >> 5;
    const int lane = threadIdx.x & 31;
    const int row  = (blockIdx.x << 3) + warp;

    float s = 0.f;
#pragma unroll
    for (int k = lane; k < 256; k += 32) {
        uint32_t u = t4[(size_t)row * 256 + k];
        float v = __half2float(__ushort_as_half((unsigned short)(u & 0xffff))) +
                  __half2float(__ushort_as_half((unsigned short)(u >> 16)));
        s = fmaf(v, __ldg(&w[k]), s);
    }
#pragma unroll
    for (int o = 16; o; o >>= 1)
        s += __shfl_down_sync(0xffffffffu, s, o);
    if (lane == 0) out[row] = s + bias[0];
}

// ---------------------------------------------------------------------------
extern "C" void kernel_launch(void* const* d_in, const int* in_sizes, int n_in,
                              void* d_out, int out_size)
{
    (void)in_sizes; (void)n_in; (void)out_size;

    const float* x   = (const float*)d_in[0];
    const float* bw0 = (const float*)d_in[2];
    const float* bb0 = (const float*)d_in[3];
    const float* bw1 = (const float*)d_in[4];
    const float* bb1 = (const float*)d_in[5];
    const float* bw2 = (const float*)d_in[6];
    const float* bb2 = (const float*)d_in[7];
    const float* emb = (const float*)d_in[8];
    const float* tw0 = (const float*)d_in[9];
    const float* tb0 = (const float*)d_in[10];
    const float* tw1 = (const float*)d_in[11];
    const float* tb1 = (const float*)d_in[12];
    const float* tw2 = (const float*)d_in[13];
    const float* tb2 = (const float*)d_in[14];
    const float* tw3 = (const float*)d_in[15];
    const float* tb3 = (const float*)d_in[16];
    const float* tw4 = (const float*)d_in[17];
    const float* tb4 = (const float*)d_in[18];
    float* out = (float*)d_out;

    uint32_t *a0, *h1, *h2, *t0, *t1, *t2, *t3, *t4;
    uint32_t *w0p, *w1p, *w2p, *tw0p, *tw1p, *tw2p, *tw3p;
    float *bot;
    cudaGetSymbolAddress((void**)&a0,   g_a0);
    cudaGetSymbolAddress((void**)&h1,   g_h1);
    cudaGetSymbolAddress((void**)&h2,   g_h2);
    cudaGetSymbolAddress((void**)&bot,  g_bot);
    cudaGetSymbolAddress((void**)&t0,   g_t0);
    cudaGetSymbolAddress((void**)&t1,   g_t1);
    cudaGetSymbolAddress((void**)&t2,   g_t2);
    cudaGetSymbolAddress((void**)&t3,   g_t3);
    cudaGetSymbolAddress((void**)&t4,   g_t4);
    cudaGetSymbolAddress((void**)&w0p,  g_w0p);
    cudaGetSymbolAddress((void**)&w1p,  g_w1p);
    cudaGetSymbolAddress((void**)&w2p,  g_w2p);
    cudaGetSymbolAddress((void**)&tw0p, g_tw0p);
    cudaGetSymbolAddress((void**)&tw1p, g_tw1p);
    cudaGetSymbolAddress((void**)&tw2p, g_tw2p);
    cudaGetSymbolAddress((void**)&tw3p, g_tw3p);

    // ---- prepass: split weights + input into packed (hi,lo) f16 ----
    auto cp = [](const float* in, uint32_t* outp, int K, int Kpad, int N) {
        int total = Kpad * N;
        conv_pack<<<(total + 255) / 256, 256>>>(in, outp, K, Kpad, N);
    };
    conv_x<<<(BATCH * 16 + 255) / 256, 256>>>(x, a0);
    cp(bw0, w0p,  13,   16,   512);
    cp(bw1, w1p,  512,  512,  256);
    cp(bw2, w2p,  256,  256,  128);
    cp(tw0, tw0p, 506,  512,  1024);
    cp(tw1, tw1p, 1024, 1024, 1024);
    cp(tw2, tw2p, 1024, 1024, 512);
    cp(tw3, tw3p, 512,  512,  256);

    const int MB = BATCH / 128;

    // bottom MLP
    gemm_hl<<<dim3(4, MB), 256>>>(a0, 16,  w0p, 512, bb0, h1,  512, 16,  1, 1);
    gemm_hl<<<dim3(2, MB), 256>>>(h1, 512, w1p, 256, bb1, h2,  256, 512, 1, 1);
    gemm_hl<<<dim3(1, MB), 256>>>(h2, 256, w2p, 128, bb2, bot, 128, 256, 1, 0);

    // gather + interaction -> t0 packed [B,512]
    interact_kernel<<<BATCH / 2, 64>>>(x, emb, bot, t0);

    // top MLP
    gemm_hl<<<dim3(8, MB), 256>>>(t0, T0LD, tw0p, 1024, tb0, t1, 1024, 512,  1, 1);
    gemm_hl<<<dim3(8, MB), 256>>>(t1, 1024, tw1p, 1024, tb1, t2, 1024, 1024, 1, 1);
    gemm_hl<<<dim3(4, MB), 256>>>(t2, 1024, tw2p, 512,  tb2, t3, 512,  1024, 1, 1);
    gemm_hl<<<dim3(2, MB), 256>>>(t3, 512,  tw3p, 256,  tb3, t4, 256,  512,  1, 1);

    // final
    final_layer<<<BATCH / 8, 256>>>(t4, tw4, tb4, out);
}